// round 2
// baseline (speedup 1.0000x reference)
#include <cuda_runtime.h>
#include <math.h>

// ---------------------------------------------------------------------------
// BatchShapingLoss, fully fused single kernel.
//   loss = sum_e (pcdf(x_e) - ecdf[rank_e])^2 / 512
// pcdf(s) = trapezoid over t_k = EPS + k*(s-EPS)/999, k=1..999 of
//           exp((a-1)ln t + (b-1)ln(1-t) - Bln), a=0.6 b=0.4
// Key points:
//  * No sort: rank_e computed by counting (stable-tie by row index).
//  * log2(t_k) ~= log2(k) + log2(h): log2(k) term is a shared SMEM table
//    -> 2 MUFU (lg2 + ex2) per quadrature point (validated: rel_err 7e-7).
//  * 512 blocks x 256 thr: all CTAs resident in one wave, no tail.
//  * Deterministic finalize: u64 fixed-point atomics + ticket, self-resetting.
// ---------------------------------------------------------------------------

#define EPSV 1e-10f

__device__ unsigned long long g_acc = 0ULL;
__device__ unsigned int       g_cnt = 0u;

static __device__ __forceinline__ float lg2f(float x) {
    float r; asm("lg2.approx.f32 %0, %1;" : "=f"(r) : "f"(x)); return r;
}
static __device__ __forceinline__ float ex2f(float x) {
    float r; asm("ex2.approx.f32 %0, %1;" : "=f"(r) : "f"(x)); return r;
}

__global__ void __launch_bounds__(256) fused_kernel(const float* __restrict__ x,
                                                    float c2 /* BETALN/ln2 */,
                                                    float* __restrict__ out)
{
    __shared__ float col[512];      // this block's column (raw, unsorted)
    __shared__ float tab[1000];     // tab[k] = -0.4 * log2(k)
    __shared__ float csum[4][64];
    __shared__ int   irnk[4][64];
    __shared__ float wsum[8];

    const float A1 = -0.4f;         // alpha - 1
    const float B1 = -0.6f;         // beta  - 1
    const float ONE = 1.0f - EPSV;

    int tid   = threadIdx.x;
    int c     = blockIdx.x >> 2;          // column 0..127
    int rbase = (blockIdx.x & 3) << 7;    // row base 0/128/256/384

    // load full column (L2-hot after first wave front) + build log2(k) table
    col[tid]       = x[tid * 128 + c];
    col[tid + 256] = x[(tid + 256) * 128 + c];
    for (int k = tid; k < 1000; k += 256)
        tab[k] = (k > 0) ? A1 * lg2f((float)k) : 0.0f;
    __syncthreads();

    int chunk = tid >> 6;                 // 0..3, uniform per warp-pair
    int el    = tid & 63;
    int k0    = 1 + chunk * 250;          // k ranges: 1-250,251-500,501-750,751-999
    int niter = (chunk == 3) ? 249 : 250;
    const float4* cp = (const float4*)col + (chunk << 5);  // this chunk's 128 col vals
    const float*  tptr = tab + k0;

    float sqacc = 0.0f;

    #pragma unroll 1
    for (int g = 0; g < 2; g++) {
        int   row = rbase + (g << 6) + el;     // element handled: (row, c)
        float s   = col[row];

        // ---- rank partial: count over col[chunk*128 .. +128) ----
        int cnt = 0;
        int jb  = chunk << 7;
        #pragma unroll 8
        for (int i = 0; i < 32; i++) {
            float4 v = cp[i];                  // warp-uniform -> LDS.128 broadcast
            int j = jb + (i << 2);
            cnt += (v.x < s) || (v.x == s && (j + 0) < row);
            cnt += (v.y < s) || (v.y == s && (j + 1) < row);
            cnt += (v.z < s) || (v.z == s && (j + 2) < row);
            cnt += (v.w < s) || (v.w == s && (j + 3) < row);
        }

        // ---- quadrature chunk ----
        float h    = (s - EPSV) * (1.0f / 999.0f);
        float base = fmaf(A1, lg2f(h), -c2);
        float kf   = (float)k0;
        float acc  = 0.0f;
        #pragma unroll 5
        for (int i = 0; i < niter; i++) {
            float u   = fmaf(kf, -h, ONE);                 // 1 - t_k
            float arg = fmaf(B1, lg2f(u), base + tptr[i]);
            acc += ex2f(arg);
            kf  += 1.0f;
        }

        csum[chunk][el] = acc;
        irnk[chunk][el] = cnt;
        __syncthreads();

        if (tid < 64) {   // chunk-0 thread: its own s/h/base are element (row,c)'s
            float S    = csum[0][el] + csum[1][el] + csum[2][el] + csum[3][el];
            int   rank = irnk[0][el] + irnk[1][el] + irnk[2][el] + irnk[3][el];
            // trapezoid endpoint corrections (tab[1] = 0)
            float p1   = ex2f(fmaf(B1, lg2f(ONE - h),              base));
            float p999 = ex2f(fmaf(B1, lg2f(fmaf(999.0f, -h, ONE)), base + tab[999]));
            float pcdf = h * (S - 0.5f * (p1 + p999));
            float ecdf = (float)(rank + 1) * (1.0f / 513.0f);
            float d    = pcdf - ecdf;
            sqacc += d * d;
        }
        __syncthreads();   // protect csum/irnk reuse in next group
    }

    // ---- deterministic block reduction ----
    float v = sqacc;
    #pragma unroll
    for (int o = 16; o > 0; o >>= 1)
        v += __shfl_xor_sync(0xffffffffu, v, o);
    if ((tid & 31) == 0) wsum[tid >> 5] = v;
    __syncthreads();

    if (tid == 0) {
        float t = wsum[0] + wsum[1] + wsum[2] + wsum[3]
                + wsum[4] + wsum[5] + wsum[6] + wsum[7];
        // fixed-point (2^42) accumulate: integer add is exactly commutative
        unsigned long long fx =
            (unsigned long long)__double2ll_rn((double)t * 4398046511104.0);
        atomicAdd(&g_acc, fx);
        __threadfence();
        unsigned int ticket = atomicAdd(&g_cnt, 1u);
        if (ticket == 511u) {    // last block: finalize + self-reset for replays
            unsigned long long tot = atomicExch(&g_acc, 0ULL);
            atomicExch(&g_cnt, 0u);
            out[0] = (float)((double)tot * (1.0 / 4398046511104.0) * (1.0 / 512.0));
        }
    }
}

extern "C" void kernel_launch(void* const* d_in, const int* in_sizes, int n_in,
                              void* d_out, int out_size) {
    const float* x = (const float*)d_in[0];
    // BETALN with the same libm lgamma the Python reference uses
    double betaln = lgamma(0.6) + lgamma(0.4) - lgamma(1.0);
    float  c2 = (float)(betaln * 1.4426950408889634);   // BETALN / ln 2

    fused_kernel<<<512, 256>>>(x, c2, (float*)d_out);
}

// round 4
// speedup vs baseline: 2.5897x; 2.5897x over previous
#include <cuda_runtime.h>
#include <math.h>

// ---------------------------------------------------------------------------
// BatchShapingLoss via series factorization.
//   pcdf(s) = C * h^0.6 * sum_j e_j z^j   (z = s-EPS, h = z/999)
//   e_j = c_j * sum_k w_k k^{-0.4} (k/999)^j,  c_j = (0.6)_j / j!
// valid (128 terms) for z <= 0.94; the ~6% of elements with z > 0.94 take the
// direct 999-point MUFU loop via a compacted worklist.
// Rank comes from a shfl+SMEM hybrid bitonic sort (rank = sorted position).
// Accumulation: fixed-point 2^42 integer atomics -> bit-deterministic.
// ---------------------------------------------------------------------------

#define EPSV   1e-10f
#define THETA  0.94f
#define NJ     128
#define K2GRID 592

__device__ float              g_e[NJ];
__device__ float2             g_wl[65536];
__device__ unsigned long long g_acc;
__device__ unsigned int       g_wlcnt;
__device__ unsigned int       g_tick;

static __device__ __forceinline__ float lg2f(float x) {
    float r; asm("lg2.approx.f32 %0, %1;" : "=f"(r) : "f"(x)); return r;
}
static __device__ __forceinline__ float ex2f(float x) {
    float r; asm("ex2.approx.f32 %0, %1;" : "=f"(r) : "f"(x)); return r;
}

// ---- kernel 0: series coefficients + global resets. grid NJ x 128 ----
__global__ void __launch_bounds__(128) coef_kernel() {
    __shared__ float wl[4], ws[4];
    int j   = blockIdx.x;
    int tid = threadIdx.x;
    if (j == 0 && tid == 0) { g_acc = 0ULL; g_wlcnt = 0u; g_tick = 0u; }

    const float L999 = 9.9643402f;   // log2(999)
    // lc partial: log2 c_j = sum_{i<j} [lg2(0.6+i) - lg2(1+i)]
    float lc = (tid < j) ? (lg2f(0.6f + (float)tid) - lg2f(1.0f + (float)tid)) : 0.0f;
    // S* partial: sum_k w_k * k^{-0.4} * (k/999)^j
    float jf = (float)j;
    float ss = 0.0f;
    for (int k = tid + 1; k <= 999; k += 128) {
        float L = lg2f((float)k);
        float w = (k == 1 || k == 999) ? 0.5f : 1.0f;
        ss += w * ex2f(fmaf(jf, L - L999, -0.4f * L));
    }
    #pragma unroll
    for (int o = 16; o > 0; o >>= 1) {
        lc += __shfl_xor_sync(0xffffffffu, lc, o);
        ss += __shfl_xor_sync(0xffffffffu, ss, o);
    }
    if ((tid & 31) == 0) { wl[tid >> 5] = lc; ws[tid >> 5] = ss; }
    __syncthreads();
    if (tid == 0) {
        float lct = wl[0] + wl[1] + wl[2] + wl[3];
        float sst = ws[0] + ws[1] + ws[2] + ws[3];
        g_e[j] = ex2f(lct) * sst;
    }
}

// ---- kernel 1: sort (rank) + series / classify. grid 128 x 512 ----
__global__ void __launch_bounds__(512) main_kernel(const float* __restrict__ x,
                                                   float Cexp /* e^{-BETALN} */)
{
    __shared__ float sm[512];
    __shared__ float ec[NJ];
    __shared__ float wsum[16];

    int tid = threadIdx.x;
    int c   = blockIdx.x;
    float v = x[tid * 128 + c];
    if (tid < NJ) ec[tid] = g_e[tid];

    // hybrid bitonic sort, ascending; rank = tid afterwards
    #pragma unroll 1
    for (int k = 2; k <= 512; k <<= 1) {
        bool up = ((tid & k) == 0);
        #pragma unroll 1
        for (int j = k >> 1; j >= 32; j >>= 1) {
            sm[tid] = v; __syncthreads();
            float u = sm[tid ^ j]; __syncthreads();
            bool lower = ((tid & j) == 0);
            v = (lower == up) ? fminf(v, u) : fmaxf(v, u);
        }
        int jmax = (k >> 1 < 16) ? (k >> 1) : 16;
        #pragma unroll 1
        for (int j = jmax; j >= 1; j >>= 1) {
            float u = __shfl_xor_sync(0xffffffffu, v, j);
            bool lower = ((tid & j) == 0);
            v = (lower == up) ? fminf(v, u) : fmaxf(v, u);
        }
    }

    float z    = v - EPSV;
    float h    = z * (1.0f / 999.0f);
    float ecdf = (float)(tid + 1) * (1.0f / 513.0f);
    float sq   = 0.0f;

    if (z <= THETA) {
        float P = ec[NJ - 1];
        #pragma unroll
        for (int j = NJ - 2; j >= 0; j--) P = fmaf(P, z, ec[j]);
        float pcdf = Cexp * ex2f(0.6f * lg2f(h)) * P;
        float d    = pcdf - ecdf;
        sq = d * d;
    } else {
        unsigned int idx = atomicAdd(&g_wlcnt, 1u);
        g_wl[idx] = make_float2(v, ecdf);
    }

    #pragma unroll
    for (int o = 16; o > 0; o >>= 1) sq += __shfl_xor_sync(0xffffffffu, sq, o);
    if ((tid & 31) == 0) wsum[tid >> 5] = sq;
    __syncthreads();
    if (tid == 0) {
        float t = 0.0f;
        #pragma unroll
        for (int w = 0; w < 16; w++) t += wsum[w];
        unsigned long long fx =
            (unsigned long long)__double2ll_rn((double)t * 4398046511104.0);
        atomicAdd(&g_acc, fx);
    }
}

// ---- kernel 2: big-z elements (direct MUFU trapezoid) + finalize ----
__global__ void __launch_bounds__(256) big_kernel(float c2 /* BETALN/ln2 */,
                                                  float* __restrict__ out)
{
    __shared__ float tab[1000];
    __shared__ float ws[8];

    int tid = threadIdx.x;
    const float ONE = 1.0f - EPSV;
    for (int k = tid + 1; k <= 999; k += 256)
        tab[k] = -0.4f * lg2f((float)k);
    __syncthreads();

    unsigned int cnt   = g_wlcnt;
    float        sqacc = 0.0f;

    for (unsigned int i = blockIdx.x; i < cnt; i += K2GRID) {
        float2 w = g_wl[i];
        float  h = (w.x - EPSV) * (1.0f / 999.0f);
        float  acc = 0.0f;
        #pragma unroll
        for (int m = 0; m < 4; m++) {
            int k = 1 + tid + (m << 8);
            if (k <= 999) {
                float u = fmaf((float)k, -h, ONE);
                acc += ex2f(fmaf(-0.6f, lg2f(u), tab[k]));
            }
        }
        #pragma unroll
        for (int o = 16; o > 0; o >>= 1) acc += __shfl_xor_sync(0xffffffffu, acc, o);
        if ((tid & 31) == 0) ws[tid >> 5] = acc;
        __syncthreads();
        if (tid == 0) {
            float S  = ws[0] + ws[1] + ws[2] + ws[3] + ws[4] + ws[5] + ws[6] + ws[7];
            float q1 = ex2f(-0.6f * lg2f(ONE - h));                             // tab[1]=0
            float q9 = ex2f(fmaf(-0.6f, lg2f(fmaf(999.0f, -h, ONE)), tab[999]));
            float sc = ex2f(fmaf(-0.4f, lg2f(h), -c2));
            float pcdf = h * sc * (S - 0.5f * (q1 + q9));
            float d    = pcdf - w.y;
            sqacc += d * d;
        }
        __syncthreads();   // ws reuse
    }

    if (tid == 0) {
        unsigned long long fx =
            (unsigned long long)__double2ll_rn((double)sqacc * 4398046511104.0);
        atomicAdd(&g_acc, fx);
        __threadfence();
        unsigned int t = atomicAdd(&g_tick, 1u);
        if (t == K2GRID - 1u) {
            unsigned long long tot = g_acc;
            out[0] = (float)((double)tot * (1.0 / 4398046511104.0) * (1.0 / 512.0));
        }
    }
}

extern "C" void kernel_launch(void* const* d_in, const int* in_sizes, int n_in,
                              void* d_out, int out_size) {
    const float* x = (const float*)d_in[0];
    double betaln = lgamma(0.6) + lgamma(0.4) - lgamma(1.0);
    float  c2   = (float)(betaln * 1.4426950408889634);  // BETALN / ln 2
    float  Cexp = (float)exp(-betaln);                   // e^{-BETALN}

    coef_kernel<<<NJ, 128>>>();
    main_kernel<<<128, 512>>>(x, Cexp);
    big_kernel<<<K2GRID, 256>>>(c2, (float*)d_out);
}

// round 7
// speedup vs baseline: 2.9086x; 1.1231x over previous
#include <cuda_runtime.h>
#include <math.h>

// ---------------------------------------------------------------------------
// BatchShapingLoss via series factorization, host-precomputed coefficients.
//   pcdf(s) = z^0.6 * sum_j E_j z^j          (z = s - EPS)
//   E_j = e^{-BETALN} 999^{-0.6} c_j 999^{-j} sum_k w_k k^{j-0.4}
// (exact reorganization of the reference's 999-point trapezoid with t_k ~ k h;
//  validated rel_err ~1e-7). Valid for z <= 0.94 with 128 terms; bigger z
// (~6% of elements) go through a compacted worklist -> direct MUFU loop,
// one element per WARP. E_j are input-independent -> computed on the host in
// double and passed as kernel parameters (coef kernel eliminated).
// Rank = position after an in-block hybrid bitonic sort.
// Accumulation: fixed-point 2^42 u64 atomics -> bit-deterministic.
// ---------------------------------------------------------------------------

#define EPSV   1e-10f
#define THETA  0.94f
#define NJ     128
#define BGRID  512
#define BBLK   256

struct Coefs { float e[NJ]; };

__device__ float2             g_wl[65536];
__device__ unsigned long long g_acc  = 0ULL;
__device__ unsigned int       g_wlcnt = 0u;
__device__ unsigned int       g_tick  = 0u;

static __device__ __forceinline__ float lg2f(float x) {
    float r; asm("lg2.approx.f32 %0, %1;" : "=f"(r) : "f"(x)); return r;
}
static __device__ __forceinline__ float ex2f(float x) {
    float r; asm("ex2.approx.f32 %0, %1;" : "=f"(r) : "f"(x)); return r;
}

// ---- kernel 1: sort (rank) + series / classify. grid 128 x 512 ----
__global__ void __launch_bounds__(512) main_kernel(const float* __restrict__ x,
                                                   const Coefs cf)
{
    __shared__ float sm[512];
    __shared__ float ec[NJ];
    __shared__ float wsum[16];

    int tid = threadIdx.x;
    int c   = blockIdx.x;
    float v = x[tid * 128 + c];
    if (tid < NJ) ec[tid] = cf.e[tid];

    // hybrid bitonic sort, ascending; rank = tid afterwards
    #pragma unroll 1
    for (int k = 2; k <= 512; k <<= 1) {
        bool up = ((tid & k) == 0);
        #pragma unroll 1
        for (int j = k >> 1; j >= 32; j >>= 1) {
            sm[tid] = v; __syncthreads();
            float u = sm[tid ^ j]; __syncthreads();
            bool lower = ((tid & j) == 0);
            v = (lower == up) ? fminf(v, u) : fmaxf(v, u);
        }
        int jmax = (k >> 1 < 16) ? (k >> 1) : 16;
        #pragma unroll 1
        for (int j = jmax; j >= 1; j >>= 1) {
            float u = __shfl_xor_sync(0xffffffffu, v, j);
            bool lower = ((tid & j) == 0);
            v = (lower == up) ? fminf(v, u) : fmaxf(v, u);
        }
    }

    float z    = v - EPSV;
    float ecdf = (float)(tid + 1) * (1.0f / 513.0f);
    float sq   = 0.0f;

    if (z <= THETA) {
        float P = ec[NJ - 1];
        #pragma unroll
        for (int j = NJ - 2; j >= 0; j--) P = fmaf(P, z, ec[j]);
        float pcdf = ex2f(0.6f * lg2f(z)) * P;
        float d    = pcdf - ecdf;
        sq = d * d;
    } else {
        unsigned int idx = atomicAdd(&g_wlcnt, 1u);
        g_wl[idx] = make_float2(v, ecdf);
    }

    #pragma unroll
    for (int o = 16; o > 0; o >>= 1) sq += __shfl_xor_sync(0xffffffffu, sq, o);
    if ((tid & 31) == 0) wsum[tid >> 5] = sq;
    __syncthreads();
    if (tid == 0) {
        float t = 0.0f;
        #pragma unroll
        for (int w = 0; w < 16; w++) t += wsum[w];
        unsigned long long fx =
            (unsigned long long)__double2ll_rn((double)t * 4398046511104.0);
        atomicAdd(&g_acc, fx);
    }
}

// ---- kernel 2: big-z elements, one per WARP; finalize + self-reset ----
__global__ void __launch_bounds__(BBLK) big_kernel(float c2 /* BETALN/ln2 */,
                                                   float* __restrict__ out)
{
    __shared__ float tab[1000];   // tab[k] = -0.4*log2(k)

    int tid = threadIdx.x;
    const float ONE = 1.0f - EPSV;
    for (int k = tid + 1; k <= 999; k += BBLK)
        tab[k] = -0.4f * lg2f((float)k);
    __syncthreads();

    int lane = tid & 31;
    unsigned int gw = (blockIdx.x * BBLK + tid) >> 5;
    unsigned int nw = (BGRID * BBLK) >> 5;
    unsigned int cnt = g_wlcnt;

    unsigned long long fx = 0ULL;

    for (unsigned int i = gw; i < cnt; i += nw) {
        float2 w = g_wl[i];
        float  h = (w.x - EPSV) * (1.0f / 999.0f);
        float  acc = 0.0f;
        // k = lane+1 + 32*m ; m=0..30 full, m=31 guarded (k max 999)
        #pragma unroll 4
        for (int m = 0; m < 31; m++) {
            int   k = lane + 1 + (m << 5);
            float u = fmaf((float)k, -h, ONE);
            acc += ex2f(fmaf(-0.6f, lg2f(u), tab[k]));
        }
        {
            int k = lane + 1 + (31 << 5);
            if (k <= 999) {
                float u = fmaf((float)k, -h, ONE);
                acc += ex2f(fmaf(-0.6f, lg2f(u), tab[k]));
            }
        }
        #pragma unroll
        for (int o = 16; o > 0; o >>= 1) acc += __shfl_xor_sync(0xffffffffu, acc, o);
        if (lane == 0) {
            float q1 = ex2f(-0.6f * lg2f(ONE - h));                              // tab[1]=0
            float q9 = ex2f(fmaf(-0.6f, lg2f(fmaf(999.0f, -h, ONE)), tab[999]));
            float sc = ex2f(fmaf(-0.4f, lg2f(h), -c2));
            float pcdf = h * sc * (acc - 0.5f * (q1 + q9));
            float d    = pcdf - w.y;
            fx += (unsigned long long)__double2ll_rn((double)(d * d) * 4398046511104.0);
        }
    }

    if (lane == 0 && fx != 0ULL) atomicAdd(&g_acc, fx);
    __syncthreads();

    if (tid == 0) {
        __threadfence();
        unsigned int t = atomicAdd(&g_tick, 1u);
        if (t == BGRID - 1u) {             // last block: finalize + reset
            __threadfence();
            unsigned long long tot = atomicExch(&g_acc, 0ULL);
            atomicExch(&g_wlcnt, 0u);
            atomicExch(&g_tick, 0u);
            out[0] = (float)((double)tot * (1.0 / 4398046511104.0) * (1.0 / 512.0));
        }
    }
}

extern "C" void kernel_launch(void* const* d_in, const int* in_sizes, int n_in,
                              void* d_out, int out_size) {
    const float* x = (const float*)d_in[0];

    double betaln = lgamma(0.6) + lgamma(0.4) - lgamma(1.0);
    float  c2 = (float)(betaln * 1.4426950408889634);   // BETALN / ln 2

    // Host-side series coefficients (double precision, input-independent):
    //   E_j = e^{-BETALN} * 999^{-0.6} * c_j * 999^{-j} * sum_k w_k k^{j-0.4}
    static Coefs cf;
    {
        double S[NJ];
        for (int j = 0; j < NJ; j++) S[j] = 0.0;
        for (int k = 1; k <= 999; k++) {
            double w = (k == 1 || k == 999) ? 0.5 : 1.0;
            double base = w * pow((double)k, -0.4);
            double r = (double)k / 999.0;
            for (int j = 0; j < NJ; j++) { S[j] += base; base *= r; }
        }
        double pref = exp(-betaln) * pow(999.0, -0.6);  // includes h^0.6 & C
        double cj = 1.0;                                 // (0.6)_j / j!
        for (int j = 0; j < NJ; j++) {
            cf.e[j] = (float)(pref * cj * S[j]);
            cj *= (0.6 + (double)j) / (1.0 + (double)j);
        }
    }

    main_kernel<<<128, 512>>>(x, cf);
    big_kernel<<<BGRID, BBLK>>>(c2, (float*)d_out);
}

// round 8
// speedup vs baseline: 3.3599x; 1.1552x over previous
#include <cuda_runtime.h>
#include <math.h>

// ---------------------------------------------------------------------------
// BatchShapingLoss, single fused kernel.
//   pcdf(s) = z^0.6 * sum_j E_j z^j   (z = s-EPS; E_j host-precomputed, exact
//   reorganization of the 999-pt trapezoid with t_k ~ k h; rel_err ~1e-7),
//   valid z <= 0.94 with 128 Horner terms.
// Big z (~6%): after the in-block bitonic sort they sit at the TOP ranks ->
//   contiguous in SMEM. The block's 16 warps process them cooperatively
//   (999 points lane-split per element, shfl-reduce). No worklist, no 2nd
//   kernel.
// Rank = sorted position. Accumulation: fixed-point 2^42 u64 atomics +
// 128-block ticket finalize (self-resetting -> graph-replay safe).
// ---------------------------------------------------------------------------

#define EPSV   1e-10f
#define THETA  0.94f
#define NJ     128

struct Coefs { float e[NJ]; };

__device__ unsigned long long g_acc  = 0ULL;
__device__ unsigned int       g_tick = 0u;

static __device__ __forceinline__ float lg2f(float x) {
    float r; asm("lg2.approx.f32 %0, %1;" : "=f"(r) : "f"(x)); return r;
}
static __device__ __forceinline__ float ex2f(float x) {
    float r; asm("ex2.approx.f32 %0, %1;" : "=f"(r) : "f"(x)); return r;
}

__global__ void __launch_bounds__(512) fused_kernel(const float* __restrict__ x,
                                                    const Coefs cf,
                                                    float c2 /* BETALN/ln2 */,
                                                    float* __restrict__ out)
{
    __shared__ float sm[512];     // scratch for sort; sorted values afterwards
    __shared__ float tab[1000];   // tab[k] = -0.4 * log2(k)
    __shared__ float ec[NJ];
    __shared__ float wsum[16];

    const float ONE = 1.0f - EPSV;
    int tid = threadIdx.x;
    int c   = blockIdx.x;

    float v = x[tid * 128 + c];
    if (tid < NJ) ec[tid] = cf.e[tid];
    for (int k = tid + 1; k <= 999; k += 512)
        tab[k] = -0.4f * lg2f((float)k);

    // hybrid bitonic sort, ascending; rank = tid afterwards
    #pragma unroll 1
    for (int k = 2; k <= 512; k <<= 1) {
        bool up = ((tid & k) == 0);
        #pragma unroll 1
        for (int j = k >> 1; j >= 32; j >>= 1) {
            sm[tid] = v; __syncthreads();
            float u = sm[tid ^ j]; __syncthreads();
            bool lower = ((tid & j) == 0);
            v = (lower == up) ? fminf(v, u) : fmaxf(v, u);
        }
        int jmax = (k >> 1 < 16) ? (k >> 1) : 16;
        #pragma unroll 1
        for (int j = jmax; j >= 1; j >>= 1) {
            float u = __shfl_xor_sync(0xffffffffu, v, j);
            bool lower = ((tid & j) == 0);
            v = (lower == up) ? fminf(v, u) : fmaxf(v, u);
        }
    }

    sm[tid] = v;                       // publish sorted values
    float z  = v - EPSV;
    int   nb = __syncthreads_count(z > THETA);   // big-z count; also fences sm

    float sq = 0.0f;

    // ---- small path: 128-term Horner (threads with big z skip) ----
    if (z <= THETA) {
        float P = ec[NJ - 1];
        #pragma unroll
        for (int j = NJ - 2; j >= 0; j--) P = fmaf(P, z, ec[j]);
        float pcdf = ex2f(0.6f * lg2f(z)) * P;
        float d    = pcdf - (float)(tid + 1) * (1.0f / 513.0f);
        sq = d * d;
    }

    // ---- big path: cooperative, one element per warp per pass ----
    int wid  = tid >> 5;
    int lane = tid & 31;
    for (int i = wid; i < nb; i += 16) {
        int   pos = 512 - nb + i;
        float s   = sm[pos];                       // broadcast
        float h   = (s - EPSV) * (1.0f / 999.0f);
        float acc = 0.0f;
        #pragma unroll 4
        for (int m = 0; m < 31; m++) {             // k = lane+1 .. 992
            int   k = lane + 1 + (m << 5);
            float u = fmaf((float)k, -h, ONE);
            acc += ex2f(fmaf(-0.6f, lg2f(u), tab[k]));
        }
        {
            int k = lane + 993;                    // k = 993..999
            if (k <= 999) {
                float u = fmaf((float)k, -h, ONE);
                acc += ex2f(fmaf(-0.6f, lg2f(u), tab[k]));
            }
        }
        #pragma unroll
        for (int o = 16; o > 0; o >>= 1) acc += __shfl_xor_sync(0xffffffffu, acc, o);
        if (lane == 0) {
            float q1 = ex2f(-0.6f * lg2f(ONE - h));                               // tab[1]=0
            float q9 = ex2f(fmaf(-0.6f, lg2f(fmaf(999.0f, -h, ONE)), tab[999]));
            float sc = ex2f(fmaf(-0.4f, lg2f(h), -c2));
            float pcdf = h * sc * (acc - 0.5f * (q1 + q9));
            float d    = pcdf - (float)(pos + 1) * (1.0f / 513.0f);
            sq += d * d;
        }
    }

    // ---- deterministic block reduction + global fixed-point accumulate ----
    #pragma unroll
    for (int o = 16; o > 0; o >>= 1) sq += __shfl_xor_sync(0xffffffffu, sq, o);
    if (lane == 0) wsum[wid] = sq;
    __syncthreads();
    if (tid == 0) {
        float t = 0.0f;
        #pragma unroll
        for (int w = 0; w < 16; w++) t += wsum[w];
        unsigned long long fx =
            (unsigned long long)__double2ll_rn((double)t * 4398046511104.0);
        atomicAdd(&g_acc, fx);
        __threadfence();
        unsigned int tk = atomicAdd(&g_tick, 1u);
        if (tk == 127u) {                      // last block: finalize + reset
            __threadfence();
            unsigned long long tot = atomicExch(&g_acc, 0ULL);
            atomicExch(&g_tick, 0u);
            out[0] = (float)((double)tot * (1.0 / 4398046511104.0) * (1.0 / 512.0));
        }
    }
}

extern "C" void kernel_launch(void* const* d_in, const int* in_sizes, int n_in,
                              void* d_out, int out_size) {
    const float* x = (const float*)d_in[0];

    double betaln = lgamma(0.6) + lgamma(0.4) - lgamma(1.0);
    float  c2 = (float)(betaln * 1.4426950408889634);   // BETALN / ln 2

    // Host-side series coefficients (double precision, input-independent):
    //   E_j = e^{-BETALN} * 999^{-0.6} * c_j * 999^{-j} * sum_k w_k k^{j-0.4}
    static Coefs cf;
    {
        double S[NJ];
        for (int j = 0; j < NJ; j++) S[j] = 0.0;
        for (int k = 1; k <= 999; k++) {
            double w = (k == 1 || k == 999) ? 0.5 : 1.0;
            double base = w * pow((double)k, -0.4);
            double r = (double)k / 999.0;
            for (int j = 0; j < NJ; j++) { S[j] += base; base *= r; }
        }
        double pref = exp(-betaln) * pow(999.0, -0.6);
        double cj = 1.0;                                 // (0.6)_j / j!
        for (int j = 0; j < NJ; j++) {
            cf.e[j] = (float)(pref * cj * S[j]);
            cj *= (0.6 + (double)j) / (1.0 + (double)j);
        }
    }

    fused_kernel<<<128, 512>>>(x, cf, c2, (float*)d_out);
}

// round 9
// speedup vs baseline: 4.6537x; 1.3851x over previous
#include <cuda_runtime.h>
#include <math.h>

// ---------------------------------------------------------------------------
// BatchShapingLoss, single fused kernel, uniform branch-free evaluation.
//   pcdf(z) = z^0.6 * (F(z) + G(z)),  z = s - EPS
//   G(z)  = sum_{k=980..999} a_k (1 - k z/999)^{-0.6}     (20 direct terms,
//           a_k = pref*w_k*k^{-0.4}, pref = e^{-BETALN} 999^{-0.6})
//   F(z)  = k<980 remainder: smooth on [0,1] (nearest pole z=999/979~1.020)
//           -> piecewise Chebyshev, 16 intervals x degree 19, host-fit in
//           double, evaluated with Clenshaw (stable).
// This is an exact reorganization of the reference's 999-pt trapezoid with
// t_k ~ k h (validated rel_err ~2e-7); Chebyshev truncation ~1e-9.
// Rank = position after in-block hybrid bitonic sort (double-buffered SMEM
// stages: ONE barrier per stage). Accumulation: fixed-point 2^42 u64 atomics,
// ticket finalize, self-resetting (graph-replay safe).
// ---------------------------------------------------------------------------

#define EPSV 1e-10f
#define NIV  16     // intervals
#define ND   20     // Chebyshev terms per interval
#define NDIR 20     // direct singular terms
#define KD0  980    // first direct k

struct Coefs {
    float ct[ND * NIV];   // Chebyshev coefs, layout [j][iv]
    float ga[NDIR];       // pref * w_k * k^-0.4
    float gb[NDIR];       // k / 999
};

__device__ unsigned long long g_acc  = 0ULL;
__device__ unsigned int       g_tick = 0u;

static __device__ __forceinline__ float lg2f(float x) {
    float r; asm("lg2.approx.f32 %0, %1;" : "=f"(r) : "f"(x)); return r;
}
static __device__ __forceinline__ float ex2f(float x) {
    float r; asm("ex2.approx.f32 %0, %1;" : "=f"(r) : "f"(x)); return r;
}

__global__ void __launch_bounds__(512) fused_kernel(const float* __restrict__ x,
                                                    const Coefs cf,
                                                    float* __restrict__ out)
{
    __shared__ float sbuf[2][512];
    __shared__ float sc[ND * NIV];
    __shared__ float wsum[16];

    int tid = threadIdx.x;
    float v = __ldg(&x[tid * 128 + blockIdx.x]);
    if (tid < ND * NIV) sc[tid] = cf.ct[tid];
    // sc reads happen after the sort's first barrier -> visible.

    // ---- hybrid bitonic sort, ascending; rank = tid afterwards ----
    // SMEM stages double-buffered: one __syncthreads per stage.
    int pb = 0;
    #pragma unroll 1
    for (int k = 2; k <= 512; k <<= 1) {
        bool up = ((tid & k) == 0);
        #pragma unroll 1
        for (int j = k >> 1; j >= 32; j >>= 1) {
            sbuf[pb][tid] = v;
            __syncthreads();
            float u = sbuf[pb][tid ^ j];
            pb ^= 1;
            bool lower = ((tid & j) == 0);
            v = (lower == up) ? fminf(v, u) : fmaxf(v, u);
        }
        int jmax = (k >> 1 < 16) ? (k >> 1) : 16;
        #pragma unroll 1
        for (int j = jmax; j >= 1; j >>= 1) {
            float u = __shfl_xor_sync(0xffffffffu, v, j);
            bool lower = ((tid & j) == 0);
            v = (lower == up) ? fminf(v, u) : fmaxf(v, u);
        }
    }

    // ---- uniform per-thread evaluation ----
    float z  = fmaxf(v - EPSV, 0.0f);
    int   iv = (int)(z * 16.0f); iv = iv > 15 ? 15 : iv;
    float w  = fmaf(32.0f, z, (float)(-(2 * iv + 1)));   // -> [-1,1]
    float tw = w + w;

    // Clenshaw: F = a0 + w*b1 - b2
    float b1 = 0.0f, b2 = 0.0f;
    #pragma unroll
    for (int j = ND - 1; j >= 1; j--) {
        float b = fmaf(tw, b1, sc[j * NIV + iv] - b2);
        b2 = b1; b1 = b;
    }
    float F = fmaf(w, b1, sc[iv] - b2);

    // 20 direct near-singular terms (constants via uniform param reads)
    float G = 0.0f;
    #pragma unroll
    for (int m = 0; m < NDIR; m++) {
        float u = fmaf(-cf.gb[m], z, 1.0f);
        G = fmaf(cf.ga[m], ex2f(-0.6f * lg2f(u)), G);
    }

    float pcdf = ex2f(0.6f * lg2f(z)) * (F + G);
    float d    = pcdf - (float)(tid + 1) * (1.0f / 513.0f);
    float sq   = d * d;

    // ---- deterministic reduction + fixed-point global accumulate ----
    #pragma unroll
    for (int o = 16; o > 0; o >>= 1) sq += __shfl_xor_sync(0xffffffffu, sq, o);
    if ((tid & 31) == 0) wsum[tid >> 5] = sq;
    __syncthreads();
    if (tid == 0) {
        float t = 0.0f;
        #pragma unroll
        for (int wi = 0; wi < 16; wi++) t += wsum[wi];
        unsigned long long fx =
            (unsigned long long)__double2ll_rn((double)t * 4398046511104.0);
        atomicAdd(&g_acc, fx);
        __threadfence();
        unsigned int tk = atomicAdd(&g_tick, 1u);
        if (tk == 127u) {                 // last block: finalize + reset
            __threadfence();
            unsigned long long tot = atomicExch(&g_acc, 0ULL);
            atomicExch(&g_tick, 0u);
            out[0] = (float)((double)tot * (1.0 / 4398046511104.0) * (1.0 / 512.0));
        }
    }
}

extern "C" void kernel_launch(void* const* d_in, const int* in_sizes, int n_in,
                              void* d_out, int out_size) {
    const float* x = (const float*)d_in[0];

    double betaln = lgamma(0.6) + lgamma(0.4) - lgamma(1.0);
    double pref   = exp(-betaln) * pow(999.0, -0.6);
    const double PI = acos(-1.0);

    Coefs cf;

    // direct singular terms k = 980..999
    for (int m = 0; m < NDIR; m++) {
        int    k = KD0 + m;
        double w = (k == 999) ? 0.5 : 1.0;
        cf.ga[m] = (float)(pref * w * pow((double)k, -0.4));
        cf.gb[m] = (float)((double)k / 999.0);
    }

    // per-k weights for the smooth part (k = 1..979), once
    static double kw[KD0];
    for (int k = 1; k < KD0; k++) {
        double w = (k == 1) ? 0.5 : 1.0;
        kw[k] = w * pow((double)k, -0.4);
    }

    // piecewise Chebyshev fit of F(z) = pref * sum_{k<980} kw_k (1-kz/999)^-0.6
    for (int ivv = 0; ivv < NIV; ivv++) {
        double zc = (ivv + 0.5) / 16.0, hl = 1.0 / 32.0;
        double fv[ND];
        for (int i = 0; i < ND; i++) {
            double xi = cos(PI * (i + 0.5) / ND);
            double zz = zc + hl * xi;
            double s  = 0.0;
            for (int k = 1; k < KD0; k++)
                s += kw[k] * pow(1.0 - (double)k * zz / 999.0, -0.6);
            fv[i] = pref * s;
        }
        for (int j = 0; j < ND; j++) {
            double a = 0.0;
            for (int i = 0; i < ND; i++)
                a += fv[i] * cos(PI * j * (i + 0.5) / ND);
            a *= 2.0 / ND;
            if (j == 0) a *= 0.5;
            cf.ct[j * NIV + ivv] = (float)a;
        }
    }

    fused_kernel<<<128, 512>>>(x, cf, (float*)d_out);
}

// round 10
// speedup vs baseline: 5.7316x; 1.2316x over previous
#include <cuda_runtime.h>
#include <math.h>

// ---------------------------------------------------------------------------
// BatchShapingLoss, single fused kernel.
// Evaluation (validated rel_err 0.0 in R9):
//   pcdf(z) = z^0.6 * (F(z) + G(z)),  z = s - EPS
//   G = 20 direct near-singular trapezoid terms (k=980..999)
//   F = k<980 remainder, smooth on [0,1] -> 16x deg-19 piecewise Chebyshev
//       (host-fit in double), Clenshaw evaluation.
// Rank (new): counting sort via 4096-bin SMEM histogram + prefix scan.
//   rank = pre[bin] + intra-bin fix (compare value, tie-break original idx
//   -> fully deterministic; atomic slot order only affects grouping).
// Accumulation: fixed-point 2^42 u64 atomics, ticket finalize, self-reset.
// ---------------------------------------------------------------------------

#define EPSV  1e-10f
#define NIV   16
#define ND    20
#define NDIR  20
#define KD0   980
#define NBINS 4096

struct Coefs {
    float ct[ND * NIV];   // Chebyshev coefs, layout [j][iv]
    float ga[NDIR];       // pref * w_k * k^-0.4
    float gb[NDIR];       // k / 999
};

__device__ unsigned long long g_acc  = 0ULL;
__device__ unsigned int       g_tick = 0u;

static __device__ __forceinline__ float lg2f(float x) {
    float r; asm("lg2.approx.f32 %0, %1;" : "=f"(r) : "f"(x)); return r;
}
static __device__ __forceinline__ float ex2f(float x) {
    float r; asm("ex2.approx.f32 %0, %1;" : "=f"(r) : "f"(x)); return r;
}

__global__ void __launch_bounds__(512) fused_kernel(const float* __restrict__ x,
                                                    const Coefs cf,
                                                    float* __restrict__ out)
{
    __shared__ unsigned int cnt[NBINS];      // counts -> then slot counters
    __shared__ unsigned int pre[NBINS + 1];  // exclusive prefix (+sentinel)
    __shared__ float        sval[512];
    __shared__ unsigned int sidx[512];
    __shared__ float        sc[ND * NIV];
    __shared__ float        wsum[16];
    __shared__ unsigned int woff[16];

    int tid = threadIdx.x;
    float v = __ldg(&x[tid * 128 + blockIdx.x]);
    if (tid < ND * NIV) sc[tid] = cf.ct[tid];

    // zero histogram (4096 u32 = 1024 uint4)
    ((uint4*)cnt)[tid]       = make_uint4(0u, 0u, 0u, 0u);
    ((uint4*)cnt)[tid + 512] = make_uint4(0u, 0u, 0u, 0u);
    __syncthreads();

    int bin = (int)(v * (float)NBINS);
    bin = bin < 0 ? 0 : (bin > NBINS - 1 ? NBINS - 1 : bin);
    atomicAdd(&cnt[bin], 1u);
    __syncthreads();

    // ---- prefix scan: 8 bins per thread ----
    uint4 a = ((uint4*)cnt)[2 * tid];
    uint4 b = ((uint4*)cnt)[2 * tid + 1];
    unsigned int e1 = a.x, e2 = e1 + a.y, e3 = e2 + a.z, e4 = e3 + a.w;
    unsigned int e5 = e4 + b.x, e6 = e5 + b.y, e7 = e6 + b.z;
    unsigned int tot = e7 + b.w;

    unsigned int incl = tot;                       // warp inclusive scan
    #pragma unroll
    for (int o = 1; o < 32; o <<= 1) {
        unsigned int n = __shfl_up_sync(0xffffffffu, incl, o);
        if ((tid & 31) >= o) incl += n;
    }
    if ((tid & 31) == 31) woff[tid >> 5] = incl;
    unsigned int wex = incl - tot;                 // exclusive within warp
    __syncthreads();
    if (tid < 16) {                                // scan the 16 warp totals
        unsigned int t = woff[tid];
        #pragma unroll
        for (int o = 1; o < 16; o <<= 1) {
            unsigned int n = __shfl_up_sync(0xffffu, t, o);
            if (tid >= o) t += n;
        }
        woff[tid] = t - woff[tid];                 // exclusive warp offsets
    }
    __syncthreads();

    unsigned int base0 = woff[tid >> 5] + wex;
    // write exclusive prefixes; cnt becomes the slot counter (same values)
    uint4 p0 = make_uint4(base0, base0 + e1, base0 + e2, base0 + e3);
    uint4 p1 = make_uint4(base0 + e4, base0 + e5, base0 + e6, base0 + e7);
    ((uint4*)pre)[2 * tid]     = p0;
    ((uint4*)pre)[2 * tid + 1] = p1;
    ((uint4*)cnt)[2 * tid]     = p0;
    ((uint4*)cnt)[2 * tid + 1] = p1;
    if (tid == 0) pre[NBINS] = 512u;
    __syncthreads();

    // ---- scatter by bin ----
    unsigned int slot = atomicAdd(&cnt[bin], 1u);
    sval[slot] = v;
    sidx[slot] = (unsigned int)tid;
    __syncthreads();

    // ---- rank ----
    unsigned int rbase = pre[bin];
    unsigned int m     = pre[bin + 1] - rbase;
    unsigned int rank  = rbase;
    if (m > 1u) {
        for (unsigned int j = rbase; j < rbase + m; j++) {
            float        vj = sval[j];
            unsigned int ij = sidx[j];
            rank += (vj < v) || (vj == v && ij < (unsigned int)tid);
        }
    }

    // ---- uniform evaluation (unchanged from R9) ----
    float z  = fmaxf(v - EPSV, 0.0f);
    int   iv = (int)(z * 16.0f); iv = iv > 15 ? 15 : iv;
    float w  = fmaf(32.0f, z, (float)(-(2 * iv + 1)));
    float tw = w + w;

    float b1 = 0.0f, b2 = 0.0f;
    #pragma unroll
    for (int j = ND - 1; j >= 1; j--) {
        float bb = fmaf(tw, b1, sc[j * NIV + iv] - b2);
        b2 = b1; b1 = bb;
    }
    float F = fmaf(w, b1, sc[iv] - b2);

    float G = 0.0f;
    #pragma unroll
    for (int mm = 0; mm < NDIR; mm++) {
        float u = fmaf(-cf.gb[mm], z, 1.0f);
        G = fmaf(cf.ga[mm], ex2f(-0.6f * lg2f(u)), G);
    }

    float pcdf = ex2f(0.6f * lg2f(z)) * (F + G);
    float d    = pcdf - (float)(rank + 1u) * (1.0f / 513.0f);
    float sq   = d * d;

    // ---- deterministic reduction + fixed-point global accumulate ----
    #pragma unroll
    for (int o = 16; o > 0; o >>= 1) sq += __shfl_xor_sync(0xffffffffu, sq, o);
    if ((tid & 31) == 0) wsum[tid >> 5] = sq;
    __syncthreads();
    if (tid == 0) {
        float t = 0.0f;
        #pragma unroll
        for (int wi = 0; wi < 16; wi++) t += wsum[wi];
        unsigned long long fx =
            (unsigned long long)__double2ll_rn((double)t * 4398046511104.0);
        atomicAdd(&g_acc, fx);
        __threadfence();
        unsigned int tk = atomicAdd(&g_tick, 1u);
        if (tk == 127u) {
            __threadfence();
            unsigned long long totacc = atomicExch(&g_acc, 0ULL);
            atomicExch(&g_tick, 0u);
            out[0] = (float)((double)totacc * (1.0 / 4398046511104.0) * (1.0 / 512.0));
        }
    }
}

extern "C" void kernel_launch(void* const* d_in, const int* in_sizes, int n_in,
                              void* d_out, int out_size) {
    const float* x = (const float*)d_in[0];

    double betaln = lgamma(0.6) + lgamma(0.4) - lgamma(1.0);
    double pref   = exp(-betaln) * pow(999.0, -0.6);
    const double PI = acos(-1.0);

    Coefs cf;

    for (int m = 0; m < NDIR; m++) {
        int    k = KD0 + m;
        double w = (k == 999) ? 0.5 : 1.0;
        cf.ga[m] = (float)(pref * w * pow((double)k, -0.4));
        cf.gb[m] = (float)((double)k / 999.0);
    }

    static double kw[KD0];
    for (int k = 1; k < KD0; k++) {
        double w = (k == 1) ? 0.5 : 1.0;
        kw[k] = w * pow((double)k, -0.4);
    }

    for (int ivv = 0; ivv < NIV; ivv++) {
        double zc = (ivv + 0.5) / 16.0, hl = 1.0 / 32.0;
        double fv[ND];
        for (int i = 0; i < ND; i++) {
            double xi = cos(PI * (i + 0.5) / ND);
            double zz = zc + hl * xi;
            double s  = 0.0;
            for (int k = 1; k < KD0; k++)
                s += kw[k] * pow(1.0 - (double)k * zz / 999.0, -0.6);
            fv[i] = pref * s;
        }
        for (int j = 0; j < ND; j++) {
            double a = 0.0;
            for (int i = 0; i < ND; i++)
                a += fv[i] * cos(PI * j * (i + 0.5) / ND);
            a *= 2.0 / ND;
            if (j == 0) a *= 0.5;
            cf.ct[j * NIV + ivv] = (float)a;
        }
    }

    fused_kernel<<<128, 512>>>(x, cf, (float*)d_out);
}